// round 15
// baseline (speedup 1.0000x reference)
#include <cuda_runtime.h>
#include <cstdint>

#define BS 32
#define NN 1024
#define FO 128
#define NWORDS 32

#define RW 4                   // rows per warp
#define BW 2                   // batches per block
#define WARPS 8                // 256 threads
#define ROWS_PER_BLOCK 32      // RW * WARPS
#define PACK_BLOCKS 512

// Scratch (no allocations allowed)
__device__ uint32_t g_adjw[NN * NWORDS];   // 128 KB packed adjacency
__device__ float    g_s2[BS * NN];         // 128 KB  s2 = c2*x
__device__ float2   g_q[BS * NN];          // 256 KB  {e2, e2*x}
__device__ float    g_c1, g_c2;
__device__ float    g_meanx[BS];

// ---------------------------------------------------------------------------
// Setup (R11-proven): pack adj; per-batch mean(x); scalars c1, c2.
// ---------------------------------------------------------------------------
__global__ void __launch_bounds__(256) k_setup(const int* __restrict__ adj,
                                               const float* __restrict__ x,
                                               const float* __restrict__ W,
                                               const float* __restrict__ a) {
    int bid = blockIdx.x;
    int tid = threadIdx.x;

    if (bid < PACK_BLOCKS) {
        int t = bid * 256 + tid;
        const int4* a4 = reinterpret_cast<const int4*>(adj);
        int4 v0 = a4[2 * t];
        int4 v1 = a4[2 * t + 1];
        uint32_t m = 0;
        m |= (v0.x > 0) ? 1u   : 0u;
        m |= (v0.y > 0) ? 2u   : 0u;
        m |= (v0.z > 0) ? 4u   : 0u;
        m |= (v0.w > 0) ? 8u   : 0u;
        m |= (v1.x > 0) ? 16u  : 0u;
        m |= (v1.y > 0) ? 32u  : 0u;
        m |= (v1.z > 0) ? 64u  : 0u;
        m |= (v1.w > 0) ? 128u : 0u;
        int lane = tid & 31;
        uint32_t val = m << ((lane & 3) * 8);
        val |= __shfl_xor_sync(0xffffffffu, val, 1);
        val |= __shfl_xor_sync(0xffffffffu, val, 2);
        uint32_t w = __shfl_sync(0xffffffffu, val, (lane & 7) * 4);
        int wbase = (t >> 5) * 8;
        if (lane < 8) g_adjw[wbase + lane] = w;
        return;
    }

    __shared__ float red[256];

    if (bid < PACK_BLOCKS + BS) {
        int b = bid - PACK_BLOCKS;
        float s = 0.f;
        for (int n = tid; n < NN; n += 256) s += x[(size_t)b * NN + n];
        red[tid] = s; __syncthreads();
        for (int st = 128; st > 0; st >>= 1) {
            if (tid < st) red[tid] += red[tid + st];
            __syncthreads();
        }
        if (tid == 0) g_meanx[b] = red[0] * (1.0f / NN);
        return;
    }

    float p = (tid < FO) ? W[tid] * a[tid] : 0.f;
    red[tid] = p; __syncthreads();
    for (int st = 128; st > 0; st >>= 1) {
        if (tid < st) red[tid] += red[tid + st];
        __syncthreads();
    }
    if (tid == 0) g_c1 = red[0];
    __syncthreads();

    p = (tid < FO) ? W[tid] * a[FO + tid] : 0.f;
    red[tid] = p; __syncthreads();
    for (int st = 128; st > 0; st >>= 1) {
        if (tid < st) red[tid] += red[tid + st];
        __syncthreads();
    }
    if (tid == 0) g_c2 = red[0];
}

// ---------------------------------------------------------------------------
// Pre: one element per thread, SoA write of s2 and {e2, e2*x}.
// ---------------------------------------------------------------------------
__global__ void __launch_bounds__(256) k_pre(const float* __restrict__ x) {
    int t = blockIdx.x * 256 + threadIdx.x;   // 0 .. BS*NN-1
    float xv = x[t];
    float c2 = g_c2;
    float s2 = c2 * xv;
    float e2 = __expf(s2);
    g_s2[t] = s2;
    g_q[t]  = make_float2(e2, e2 * xv);
}

// ---------------------------------------------------------------------------
// Main: 512 blocks x 256 thr — entire grid resident in ONE wave (4 blk/SM).
// Warp = 4 rows x 2 batches. Loop body has NO exp/mul: LDS.32 s2 + LDS.64
// {e2,e2x} per (b,kk); adj via transposed LDS.128; pairs = FSETP + 2 @p FADD.
// Keep-predicate identical: adj bit && (s2_j > -c1*x_i).
// ---------------------------------------------------------------------------
__device__ __forceinline__ float elu_fast(float v) {
    return v > 0.f ? v : (__expf(v) - 1.0f);
}

__global__ void __launch_bounds__(256, 4) k_main(const float* __restrict__ x,
                                                 const float* __restrict__ W,
                                                 float* __restrict__ out) {
    __shared__ float    s_s2[BW][NN];                    // 8 KB
    __shared__ float2   s_q[BW][NN];                     // 16 KB
    __shared__ uint32_t s_adjT[NWORDS][ROWS_PER_BLOCK];  // 4 KB [word][row]
    __shared__ float    s_W[FO];                         // 512 B

    int tid  = threadIdx.x;
    int lane = tid & 31;
    int warp = tid >> 5;
    int row0 = blockIdx.x * ROWS_PER_BLOCK;
    int b0   = blockIdx.y * BW;

    // cooperative fills (SoA, vectorized)
    {
        const float4* src = reinterpret_cast<const float4*>(&g_s2[(size_t)b0 * NN]);
        float4* dst = reinterpret_cast<float4*>(&s_s2[0][0]);
        for (int t = tid; t < BW * NN / 4; t += 256) dst[t] = src[t];
    }
    {
        const float4* src = reinterpret_cast<const float4*>(&g_q[(size_t)b0 * NN]);
        float4* dst = reinterpret_cast<float4*>(&s_q[0][0]);
        for (int t = tid; t < BW * NN / 2; t += 256) dst[t] = src[t];
    }
    for (int t = tid; t < ROWS_PER_BLOCK * NWORDS; t += 256) {
        int kk = t >> 5, r = t & 31;
        s_adjT[kk][r] = g_adjw[(row0 + r) * NWORDS + kk];
    }
    if (tid < FO) s_W[tid] = W[tid];
    __syncthreads();

    const float c1 = g_c1;
    const int ir = warp * RW;
    const uint32_t lanebit = 1u << lane;

    float thr[RW][BW], den[RW][BW], num[RW][BW];
#pragma unroll
    for (int r = 0; r < RW; r++)
#pragma unroll
        for (int b = 0; b < BW; b++) {
            thr[r][b] = -c1 * x[(size_t)(b0 + b) * NN + row0 + ir + r];
            den[r][b] = 0.f;
            num[r][b] = 0.f;
        }

#pragma unroll 8
    for (int kk = 0; kk < NWORDS; kk++) {
        uint4 w4 = *reinterpret_cast<const uint4*>(&s_adjT[kk][ir]);  // LDS.128
        bool p0 = (w4.x & lanebit) != 0;
        bool p1 = (w4.y & lanebit) != 0;
        bool p2 = (w4.z & lanebit) != 0;
        bool p3 = (w4.w & lanebit) != 0;
#pragma unroll
        for (int b = 0; b < BW; b++) {
            int j = kk * 32 + lane;
            float  s2 = s_s2[b][j];     // LDS.32
            float2 q  = s_q[b][j];      // LDS.64 {e2, e2x}
            if (p0 && (s2 > thr[0][b])) { den[0][b] += q.x; num[0][b] += q.y; }
            if (p1 && (s2 > thr[1][b])) { den[1][b] += q.x; num[1][b] += q.y; }
            if (p2 && (s2 > thr[2][b])) { den[2][b] += q.x; num[2][b] += q.y; }
            if (p3 && (s2 > thr[3][b])) { den[3][b] += q.x; num[3][b] += q.y; }
        }
    }

    const float4 wv = reinterpret_cast<const float4*>(s_W)[lane];

#pragma unroll
    for (int r = 0; r < RW; r++) {
        int i = row0 + ir + r;
#pragma unroll
        for (int b = 0; b < BW; b++) {
            float d = den[r][b], nm = num[r][b];
#pragma unroll
            for (int o = 16; o > 0; o >>= 1) {
                d  += __shfl_xor_sync(0xffffffffu, d,  o);
                nm += __shfl_xor_sync(0xffffffffu, nm, o);
            }
            float y = (d > 0.f) ? __fdividef(nm, d) : g_meanx[b0 + b];
            float4 z;
            z.x = elu_fast(y * wv.x);
            z.y = elu_fast(y * wv.y);
            z.z = elu_fast(y * wv.z);
            z.w = elu_fast(y * wv.w);
            reinterpret_cast<float4*>(out)[((size_t)(b0 + b) * NN + i) * (FO / 4) + lane] = z;
        }
    }
}

// ---------------------------------------------------------------------------
// Inputs per metadata order: input, adj, ext_input, side_input, W, a
// ---------------------------------------------------------------------------
extern "C" void kernel_launch(void* const* d_in, const int* in_sizes, int n_in,
                              void* d_out, int out_size) {
    const float* input = (const float*)d_in[0];
    const int*   adj   = (const int*)  d_in[1];
    const float* W     = (const float*)d_in[4];
    const float* a     = (const float*)d_in[5];
    float* out = (float*)d_out;

    k_setup<<<PACK_BLOCKS + BS + 1, 256>>>(adj, input, W, a);
    k_pre<<<BS * NN / 256, 256>>>(input);
    k_main<<<dim3(NN / ROWS_PER_BLOCK, BS / BW), 256>>>(input, W, out);
}

// round 16
// speedup vs baseline: 1.6186x; 1.6186x over previous
#include <cuda_runtime.h>
#include <cstdint>

#define BS 32
#define NN 1024
#define FO 128
#define NWORDS 32

#define RW 4                   // rows per warp
#define BW 2                   // batches per block
#define ROWS_PER_BLOCK 8       // 2 row-groups x RW
#define KHALF 16               // words per kk-half
#define PACK_BLOCKS 512

// Scratch (no allocations allowed)
__device__ uint32_t g_adjw[NN * NWORDS];   // 128 KB packed adjacency
__device__ float    g_c1, g_c2;
__device__ float    g_meanx[BS];

// ---------------------------------------------------------------------------
// Setup (R14-proven): pack adj via 2x LDG.128/thread + shfl byte-pack;
// per-batch mean(x); scalars c1, c2.
// ---------------------------------------------------------------------------
__global__ void __launch_bounds__(256) k_setup(const int* __restrict__ adj,
                                               const float* __restrict__ x,
                                               const float* __restrict__ W,
                                               const float* __restrict__ a) {
    int bid = blockIdx.x;
    int tid = threadIdx.x;

    if (bid < PACK_BLOCKS) {
        int t = bid * 256 + tid;
        const int4* a4 = reinterpret_cast<const int4*>(adj);
        int4 v0 = a4[2 * t];
        int4 v1 = a4[2 * t + 1];
        uint32_t m = 0;
        m |= (v0.x > 0) ? 1u   : 0u;
        m |= (v0.y > 0) ? 2u   : 0u;
        m |= (v0.z > 0) ? 4u   : 0u;
        m |= (v0.w > 0) ? 8u   : 0u;
        m |= (v1.x > 0) ? 16u  : 0u;
        m |= (v1.y > 0) ? 32u  : 0u;
        m |= (v1.z > 0) ? 64u  : 0u;
        m |= (v1.w > 0) ? 128u : 0u;
        int lane = tid & 31;
        uint32_t val = m << ((lane & 3) * 8);
        val |= __shfl_xor_sync(0xffffffffu, val, 1);
        val |= __shfl_xor_sync(0xffffffffu, val, 2);
        uint32_t w = __shfl_sync(0xffffffffu, val, (lane & 7) * 4);
        int wbase = (t >> 5) * 8;
        if (lane < 8) g_adjw[wbase + lane] = w;
        return;
    }

    __shared__ float red[256];

    if (bid < PACK_BLOCKS + BS) {
        int b = bid - PACK_BLOCKS;
        float s = 0.f;
        for (int n = tid; n < NN; n += 256) s += x[(size_t)b * NN + n];
        red[tid] = s; __syncthreads();
        for (int st = 128; st > 0; st >>= 1) {
            if (tid < st) red[tid] += red[tid + st];
            __syncthreads();
        }
        if (tid == 0) g_meanx[b] = red[0] * (1.0f / NN);
        return;
    }

    float p = (tid < FO) ? W[tid] * a[tid] : 0.f;
    red[tid] = p; __syncthreads();
    for (int st = 128; st > 0; st >>= 1) {
        if (tid < st) red[tid] += red[tid + st];
        __syncthreads();
    }
    if (tid == 0) g_c1 = red[0];
    __syncthreads();

    p = (tid < FO) ? W[tid] * a[FO + tid] : 0.f;
    red[tid] = p; __syncthreads();
    for (int st = 128; st > 0; st >>= 1) {
        if (tid < st) red[tid] += red[tid + st];
        __syncthreads();
    }
    if (tid == 0) g_c2 = red[0];
}

// ---------------------------------------------------------------------------
// Main: 2048 blocks x 128 thr (R11 residency geometry, 12 blocks/SM).
// 4 warps = 2 row-groups x 2 kk-halves. Each warp runs the lean RW4/BW2 body
// (LDS.128 adj serves 4 rows; one exp serves 4 pairs) over 16 words.
// kk-halves combine via smem; lower warps reduce + write.
// Keep-predicate identical: adj bit && (c2*x_j > -c1*x_i).
// ---------------------------------------------------------------------------
__device__ __forceinline__ float elu_fast(float v) {
    return v > 0.f ? v : (__expf(v) - 1.0f);
}

__global__ void __launch_bounds__(128, 12) k_main(const float* __restrict__ x,
                                                  const float* __restrict__ W,
                                                  float* __restrict__ out) {
    __shared__ float    s_x[BW][NN];                      // 8 KB
    __shared__ uint32_t s_adjT[NWORDS][ROWS_PER_BLOCK];   // 1 KB [word][row]
    __shared__ float    s_W[FO];                          // 512 B
    __shared__ float2   s_part[2][RW * BW][32];           // 4 KB [wg][pair][lane]

    int tid  = threadIdx.x;
    int lane = tid & 31;
    int warp = tid >> 5;
    int wg   = warp & 1;        // row-group
    int half = warp >> 1;       // kk-half
    int row0 = blockIdx.x * ROWS_PER_BLOCK;
    int b0   = blockIdx.y * BW;

    // cooperative loads
    {
        const float4* src = reinterpret_cast<const float4*>(x + (size_t)b0 * NN);
        float4* dst = reinterpret_cast<float4*>(&s_x[0][0]);
        for (int t = tid; t < BW * NN / 4; t += 128) dst[t] = src[t];
    }
    {
        int r = tid >> 5, kk = tid & 31;
        s_adjT[kk][r]     = g_adjw[(row0 + r) * NWORDS + kk];
        s_adjT[kk][r + 4] = g_adjw[(row0 + r + 4) * NWORDS + kk];
    }
    s_W[tid] = W[tid];
    __syncthreads();

    const float c1 = g_c1, c2 = g_c2;
    const int ir = wg * RW;
    const uint32_t lanebit = 1u << lane;

    float thr[RW][BW], den[RW][BW], num[RW][BW];
#pragma unroll
    for (int r = 0; r < RW; r++)
#pragma unroll
        for (int b = 0; b < BW; b++) {
            thr[r][b] = -c1 * s_x[b][row0 + ir + r];
            den[r][b] = 0.f;
            num[r][b] = 0.f;
        }

    const int kk0 = half * KHALF;
#pragma unroll
    for (int kk = 0; kk < KHALF; kk++) {
        int k = kk0 + kk;
        uint4 w4 = *reinterpret_cast<const uint4*>(&s_adjT[k][ir]);  // LDS.128
        bool p0 = (w4.x & lanebit) != 0;
        bool p1 = (w4.y & lanebit) != 0;
        bool p2 = (w4.z & lanebit) != 0;
        bool p3 = (w4.w & lanebit) != 0;
#pragma unroll
        for (int b = 0; b < BW; b++) {
            float xv = s_x[b][k * 32 + lane];
            float s2 = c2 * xv;
            float e2 = __expf(s2);
            if (p0 && (s2 > thr[0][b])) { den[0][b] += e2; num[0][b] = fmaf(e2, xv, num[0][b]); }
            if (p1 && (s2 > thr[1][b])) { den[1][b] += e2; num[1][b] = fmaf(e2, xv, num[1][b]); }
            if (p2 && (s2 > thr[2][b])) { den[2][b] += e2; num[2][b] = fmaf(e2, xv, num[2][b]); }
            if (p3 && (s2 > thr[3][b])) { den[3][b] += e2; num[3][b] = fmaf(e2, xv, num[3][b]); }
        }
    }

    // kk-half combine: upper half stores per-lane partials, lower half adds.
    if (half == 1) {
#pragma unroll
        for (int r = 0; r < RW; r++)
#pragma unroll
            for (int b = 0; b < BW; b++)
                s_part[wg][r * BW + b][lane] = make_float2(den[r][b], num[r][b]);
    }
    __syncthreads();

    if (half == 0) {
#pragma unroll
        for (int r = 0; r < RW; r++)
#pragma unroll
            for (int b = 0; b < BW; b++) {
                float2 p = s_part[wg][r * BW + b][lane];
                den[r][b] += p.x;
                num[r][b] += p.y;
            }

        const float4 wv = reinterpret_cast<const float4*>(s_W)[lane];

#pragma unroll
        for (int r = 0; r < RW; r++) {
            int i = row0 + ir + r;
#pragma unroll
            for (int b = 0; b < BW; b++) {
                float d = den[r][b], nm = num[r][b];
#pragma unroll
                for (int o = 16; o > 0; o >>= 1) {
                    d  += __shfl_xor_sync(0xffffffffu, d,  o);
                    nm += __shfl_xor_sync(0xffffffffu, nm, o);
                }
                float y = (d > 0.f) ? __fdividef(nm, d) : g_meanx[b0 + b];
                float4 z;
                z.x = elu_fast(y * wv.x);
                z.y = elu_fast(y * wv.y);
                z.z = elu_fast(y * wv.z);
                z.w = elu_fast(y * wv.w);
                reinterpret_cast<float4*>(out)[((size_t)(b0 + b) * NN + i) * (FO / 4) + lane] = z;
            }
        }
    }
}

// ---------------------------------------------------------------------------
// Inputs per metadata order: input, adj, ext_input, side_input, W, a
// ---------------------------------------------------------------------------
extern "C" void kernel_launch(void* const* d_in, const int* in_sizes, int n_in,
                              void* d_out, int out_size) {
    const float* input = (const float*)d_in[0];
    const int*   adj   = (const int*)  d_in[1];
    const float* W     = (const float*)d_in[4];
    const float* a     = (const float*)d_in[5];
    float* out = (float*)d_out;

    k_setup<<<PACK_BLOCKS + BS + 1, 256>>>(adj, input, W, a);
    k_main<<<dim3(NN / ROWS_PER_BLOCK, BS / BW), 128>>>(input, W, out);
}